// round 1
// baseline (speedup 1.0000x reference)
#include <cuda_runtime.h>
#include <cstddef>

#define Bn     4
#define Cn     64
#define Hn     512
#define Wn     512
#define NSPIX  256
#define HW     (Hn*Wn)
#define Pn     (Hn*Wn)
#define FSTRIDE 257   // 256 pixels + 1 pad -> conflict-free both directions

// scratch (no allocations allowed)
__device__ float g_spix [Bn*NSPIX*Cn];
__device__ float g_numer[Bn*NSPIX*Cn];
__device__ float g_denom[Bn*NSPIX];

// ---------------------------------------------------------------------------
// init: superpixel centroids = 32x32 block means of f
// block = (cell s, batch b), 256 threads: thread = (channel c, row-quarter)
// ---------------------------------------------------------------------------
__global__ void init_kernel(const float* __restrict__ f)
{
    __shared__ float sm[256];
    const int s = blockIdx.x, b = blockIdx.y;
    const int tid = threadIdx.x;
    const int c = tid & 63, part = tid >> 6;
    const int R = s >> 4, Cc = s & 15;
    const int y0 = R*32 + part*8, x0 = Cc*32;
    const float* fp = f + ((size_t)(b*Cn + c))*HW + (size_t)y0*Wn + x0;

    float sum = 0.f;
    for (int yy = 0; yy < 8; yy++) {
        const float4* r = (const float4*)(fp + (size_t)yy*Wn);
        #pragma unroll
        for (int x4 = 0; x4 < 8; x4++) {
            float4 v = r[x4];
            sum += (v.x + v.y) + (v.z + v.w);
        }
    }
    sm[tid] = sum;
    __syncthreads();
    if (tid < 64) {
        float t = sm[tid] + sm[64+tid] + sm[128+tid] + sm[192+tid];
        g_spix[(b*NSPIX + s)*Cn + tid] = t * (1.0f/1024.0f);
    }
}

__global__ void zero_kernel()
{
    int idx = blockIdx.x*256 + threadIdx.x;
    if (idx < Bn*NSPIX*Cn) g_numer[idx] = 0.f;
    if (idx < Bn*NSPIX)    g_denom[idx] = 0.f;
}

// ---------------------------------------------------------------------------
// fused iteration kernel
// grid = (q=4 row-quarters, cell=256, b=4); block = 256 threads = 8x32 pixels
// ---------------------------------------------------------------------------
__global__ __launch_bounds__(256, 2)
void ssn_iter_kernel(const float* __restrict__ f,
                     float* __restrict__ out_labels,
                     int last)
{
    extern __shared__ float smbuf[];
    float* sh_f   = smbuf;                       // [64][FSTRIDE]  (c-major)
    float* sh_g   = sh_f  + 64*FSTRIDE;          // [9][64]  (16B aligned)
    float* sh_w   = sh_g  + 9*64;                // [9][256]
    float* sh_M   = sh_w  + 9*256;               // [9][64]
    float* sh_gsq = sh_M  + 9*64;                // [9]
    float* sh_red = sh_gsq + 9;                  // [9][8]

    const int tid  = threadIdx.x;
    const int lane = tid & 31, wid = tid >> 5;
    const int b = blockIdx.z, cell = blockIdx.y, q = blockIdx.x;
    const int R = cell >> 4, Cc = cell & 15;
    const int y0 = R*32 + q*8, x0 = Cc*32;
    const int ty = tid >> 5, tx = tid & 31;      // pixel p == tid

    int  nbr[9];
    bool valid[9];
    #pragma unroll
    for (int k = 0; k < 9; k++) {
        int rr = R + k/3 - 1, cc = Cc + (k%3) - 1;
        bool v = (rr >= 0) & (rr < 16) & (cc >= 0) & (cc < 16);
        valid[k] = v;
        nbr[k]   = v ? rr*16 + cc : 0;
    }

    // phase 0: load 9 neighbor centroids, zero M, stage f tile
    for (int idx = tid; idx < 576; idx += 256) {
        int k = idx >> 6;
        sh_g[idx] = valid[k] ? g_spix[(b*NSPIX + nbr[k])*Cn + (idx & 63)] : 0.f;
        sh_M[idx] = 0.f;
    }
    float s_v = 0.f;
    {
        const float* fp = f + ((size_t)b*Cn)*HW + (size_t)(y0+ty)*Wn + (x0+tx);
        #pragma unroll 8
        for (int c = 0; c < 64; c++) {
            float v = fp[(size_t)c*HW];          // coalesced over tx
            sh_f[c*FSTRIDE + tid] = v;
            s_v += v*v;
        }
    }
    __syncthreads();
    if (tid < 9) {
        float s = 0.f;
        #pragma unroll
        for (int c = 0; c < 64; c++) { float gv = sh_g[tid*64 + c]; s += gv*gv; }
        sh_gsq[tid] = s;
    }
    __syncthreads();

    // phase 1: dist via ||f||^2 - 2 f.g + ||g||^2, then softmax over k
    float acc[9];
    #pragma unroll
    for (int k = 0; k < 9; k++) acc[k] = 0.f;

    #pragma unroll 4
    for (int c4 = 0; c4 < 64; c4 += 4) {
        float v0 = sh_f[(c4+0)*FSTRIDE + tid];
        float v1 = sh_f[(c4+1)*FSTRIDE + tid];
        float v2 = sh_f[(c4+2)*FSTRIDE + tid];
        float v3 = sh_f[(c4+3)*FSTRIDE + tid];
        #pragma unroll
        for (int k = 0; k < 9; k++) {
            float4 g4 = *(const float4*)&sh_g[k*64 + c4];   // broadcast LDS.128
            acc[k] += v0*g4.x;
            acc[k] += v1*g4.y;
            acc[k] += v2*g4.z;
            acc[k] += v3*g4.w;
        }
    }

    float dmin = 3.0e38f;
    #pragma unroll
    for (int k = 0; k < 9; k++) {
        float d = valid[k] ? (s_v - 2.f*acc[k] + sh_gsq[k]) : 3.0e38f;
        acc[k] = d;
        dmin = fminf(dmin, d);
    }

    if (last) {  // argmax(affinity) == first argmin(dist) among valid
        int kb = 0; float bd = acc[0];
        #pragma unroll
        for (int k = 1; k < 9; k++) if (acc[k] < bd) { bd = acc[k]; kb = k; }
        out_labels[(size_t)b*Pn + (size_t)(y0+ty)*Wn + (x0+tx)] = (float)nbr[kb];
    }

    float wsum = 0.f;
    #pragma unroll
    for (int k = 0; k < 9; k++) {
        float e = __expf(dmin - acc[k]);   // invalid -> exp(-huge) = 0
        acc[k] = e;
        wsum += e;
    }
    float inv = 1.f / wsum;
    #pragma unroll
    for (int k = 0; k < 9; k++) {
        float wk = acc[k] * inv;
        acc[k] = wk;
        sh_w[k*256 + tid] = wk;
    }

    // denom: block-reduce each of the 9 weights over 256 pixels
    #pragma unroll
    for (int k = 0; k < 9; k++) {
        float s = acc[k];
        s += __shfl_down_sync(0xffffffffu, s, 16);
        s += __shfl_down_sync(0xffffffffu, s, 8);
        s += __shfl_down_sync(0xffffffffu, s, 4);
        s += __shfl_down_sync(0xffffffffu, s, 2);
        s += __shfl_down_sync(0xffffffffu, s, 1);
        if (lane == 0) sh_red[k*8 + wid] = s;
    }
    __syncthreads();   // also orders sh_w writes before phase 2
    if (tid < 9 && valid[tid]) {
        float s = 0.f;
        #pragma unroll
        for (int j = 0; j < 8; j++) s += sh_red[tid*8 + j];
        atomicAdd(&g_denom[b*NSPIX + nbr[tid]], s);
    }

    // phase 2: warp-private M[k][c] over 32 pixels; lane owns c=lane, c=lane+32
    float m0[9], m1[9];
    #pragma unroll
    for (int k = 0; k < 9; k++) { m0[k] = 0.f; m1[k] = 0.f; }
    const int p0 = wid * 32;
    for (int j = 0; j < 32; j++) {
        int p = p0 + j;
        float v0 = sh_f[ lane      *FSTRIDE + p];   // conflict-free
        float v1 = sh_f[(lane + 32)*FSTRIDE + p];
        #pragma unroll
        for (int k = 0; k < 9; k++) {
            float wk = sh_w[k*256 + p];             // broadcast
            m0[k] += wk * v0;
            m1[k] += wk * v1;
        }
    }
    #pragma unroll
    for (int k = 0; k < 9; k++) {
        atomicAdd(&sh_M[k*64 + lane],      m0[k]);
        atomicAdd(&sh_M[k*64 + lane + 32], m1[k]);
    }
    __syncthreads();

    for (int idx = tid; idx < 576; idx += 256) {
        int k = idx >> 6;
        if (valid[k])
            atomicAdd(&g_numer[(b*NSPIX + nbr[k])*Cn + (idx & 63)], sh_M[idx]);
    }
}

// ---------------------------------------------------------------------------
__global__ void update_kernel(float* __restrict__ out_spix, int last)
{
    int idx = blockIdx.x*256 + threadIdx.x;     // 65536 total
    float val = g_numer[idx] / (g_denom[idx >> 6] + 1e-16f);
    g_spix[idx] = val;
    if (last) out_spix[idx] = val;
}

// ---------------------------------------------------------------------------
extern "C" void kernel_launch(void* const* d_in, const int* in_sizes, int n_in,
                              void* d_out, int out_size)
{
    const float* f = (const float*)d_in[0];
    float* out        = (float*)d_out;
    float* out_spix   = out;                       // (4,256,64)
    float* out_labels = out + Bn*NSPIX*Cn;         // (4,262144)

    const int SMEM_BYTES = (64*FSTRIDE + 9*64 + 9*256 + 9*64 + 9 + 9*8) * 4;
    cudaFuncSetAttribute(ssn_iter_kernel,
                         cudaFuncAttributeMaxDynamicSharedMemorySize, SMEM_BYTES);

    init_kernel<<<dim3(NSPIX, Bn), 256>>>(f);
    for (int it = 0; it < 5; it++) {
        zero_kernel<<<256, 256>>>();
        ssn_iter_kernel<<<dim3(4, NSPIX, Bn), 256, SMEM_BYTES>>>(f, out_labels, it == 4);
        update_kernel<<<256, 256>>>(out_spix, it == 4);
    }
}

// round 2
// speedup vs baseline: 1.0826x; 1.0826x over previous
#include <cuda_runtime.h>
#include <cstddef>

#define Bn     4
#define Cn     64
#define Hn     512
#define Wn     512
#define NSPIX  256
#define HW     (Hn*Wn)
#define S      258           // smem pixel stride (even: 8B-aligned pairs, conflict-free)

typedef unsigned long long ull;

// scratch (no allocations allowed)
__device__ float g_spix [Bn*NSPIX*Cn];
__device__ float g_numer[Bn*NSPIX*Cn];
__device__ float g_denom2[2][Bn*NSPIX];

// ---- packed fp32x2 helpers (Blackwell FFMA2) --------------------------------
__device__ __forceinline__ ull f2_pack(float a, float b) {
    ull r; asm("mov.b64 %0, {%1,%2};" : "=l"(r) : "f"(a), "f"(b)); return r;
}
__device__ __forceinline__ void f2_unpack(ull v, float& a, float& b) {
    asm("mov.b64 {%0,%1}, %2;" : "=f"(a), "=f"(b) : "l"(v));
}
__device__ __forceinline__ void ffma2(ull& d, ull a, ull b) {
    asm("fma.rn.f32x2 %0, %1, %2, %0;" : "+l"(d) : "l"(a), "l"(b));
}

// shared layout (float offsets)
#define OFF_F    0                    // [64][258]
#define OFF_G2   16512                // [9][64] float2 (g,g)
#define OFF_W2   17664                // [128 pairs][20]  (9 float2 + pad)
#define OFF_M    20224                // [9][64]
#define OFF_RED  20800                // [128][18]  phase-1 partials (float2 x9)
#define OFF_SV   23104                // [256]
#define OFF_GSQ  23360                // [16]
#define OFF_DRED 23376                // [9][4] + pad
#define SMEM_FLOATS 23416
#define SMEM_BYTES  (SMEM_FLOATS*4)

// ---------------------------------------------------------------------------
// init: centroids = 32x32 block means; also zero numer/denom buffers
// ---------------------------------------------------------------------------
__global__ void init_kernel(const float* __restrict__ f)
{
    __shared__ float sm[256];
    const int s = blockIdx.x, b = blockIdx.y;
    const int tid = threadIdx.x;
    const int c = tid & 63, part = tid >> 6;
    const int R = s >> 4, Cc = s & 15;
    const int y0 = R*32 + part*8, x0 = Cc*32;
    const float* fp = f + ((size_t)(b*Cn + c))*HW + (size_t)y0*Wn + x0;

    float sum = 0.f;
    for (int yy = 0; yy < 8; yy++) {
        const float4* r = (const float4*)(fp + (size_t)yy*Wn);
        #pragma unroll
        for (int x4 = 0; x4 < 8; x4++) {
            float4 v = r[x4];
            sum += (v.x + v.y) + (v.z + v.w);
        }
    }
    sm[tid] = sum;

    int gid = ((blockIdx.y*gridDim.x) + blockIdx.x)*256 + tid;
    if (gid < Bn*NSPIX*Cn) g_numer[gid] = 0.f;
    if (gid < 2*Bn*NSPIX)  ((float*)g_denom2)[gid] = 0.f;

    __syncthreads();
    if (tid < 64) {
        float t = sm[tid] + sm[64+tid] + sm[128+tid] + sm[192+tid];
        g_spix[(b*NSPIX + s)*Cn + tid] = t * (1.0f/1024.0f);
    }
}

// ---------------------------------------------------------------------------
// fused iteration kernel.  grid=(4,256,4)  block=256 (8x32 pixel tile)
// ---------------------------------------------------------------------------
__global__ __launch_bounds__(256, 2)
void ssn_iter_kernel(const float* __restrict__ f,
                     float* __restrict__ out_labels,
                     int it, int last)
{
    extern __shared__ float smbuf[];
    float* sh_f    = smbuf + OFF_F;
    float* sh_g2   = smbuf + OFF_G2;
    float* sh_w2   = smbuf + OFF_W2;
    float* sh_M    = smbuf + OFF_M;
    float* sh_red  = smbuf + OFF_RED;
    float* sh_sv   = smbuf + OFF_SV;
    float* sh_gsq  = smbuf + OFF_GSQ;
    float* sh_dred = smbuf + OFF_DRED;

    const int tid = threadIdx.x;
    const int bb = blockIdx.z, cell = blockIdx.y, q = blockIdx.x;
    const int R = cell >> 4, Cc = cell & 15;
    const int y0 = R*32 + q*8, x0 = Cc*32;
    const int par = it & 1;

    int  nbr[9];
    bool valid[9];
    #pragma unroll
    for (int k = 0; k < 9; k++) {
        int rr = R + k/3 - 1, cc = Cc + (k%3) - 1;
        bool v = (rr >= 0) & (rr < 16) & (cc >= 0) & (cc < 16);
        valid[k] = v;
        nbr[k]   = v ? rr*16 + cc : 0;
    }

    // phase 0: duplicate centroids as (g,g) pairs, zero M, stage f + ||f||^2
    for (int idx = tid; idx < 576; idx += 256) {
        int k = idx >> 6;
        float g = valid[k] ? g_spix[(bb*NSPIX + nbr[k])*Cn + (idx & 63)] : 0.f;
        sh_g2[idx*2]   = g;
        sh_g2[idx*2+1] = g;
        sh_M[idx] = 0.f;
    }
    {
        const int ty = tid >> 5, tx = tid & 31;
        const float* fp = f + ((size_t)bb*Cn)*HW + (size_t)(y0+ty)*Wn + (x0+tx);
        float sv = 0.f;
        #pragma unroll 16
        for (int c = 0; c < 64; c++) {
            float v = fp[(size_t)c*HW];
            sh_f[c*S + tid] = v;
            sv += v*v;
        }
        sh_sv[tid] = sv;
    }
    __syncthreads();

    // phase 1: packed dot products. thread = (pixel pair pi, channel half h)
    const int pi = tid & 127, h = tid >> 7;
    ull acc[9];
    #pragma unroll
    for (int k = 0; k < 9; k++) acc[k] = 0ull;
    {
        const int cbase = h << 5;
        #pragma unroll 2
        for (int c2 = 0; c2 < 32; c2 += 2) {
            int c = cbase + c2;
            ull v0 = *(const ull*)&sh_f[c*S     + 2*pi];
            ull v1 = *(const ull*)&sh_f[(c+1)*S + 2*pi];
            #pragma unroll
            for (int k = 0; k < 9; k++) {
                ulonglong2 g = *(const ulonglong2*)&sh_g2[(k*64 + c)*2];
                ffma2(acc[k], v0, g.x);
                ffma2(acc[k], v1, g.y);
            }
        }
    }
    if (h == 1) {
        #pragma unroll
        for (int k = 0; k < 9; k++)
            *(ull*)&sh_red[pi*18 + 2*k] = acc[k];
    }
    if (tid < 9) {                       // ||g||^2 (reads sh_g2, valid here)
        float s = 0.f;
        #pragma unroll
        for (int c = 0; c < 64; c++) { float gv = sh_g2[(tid*64 + c)*2]; s += gv*gv; }
        sh_gsq[tid] = s;
    }
    __syncthreads();

    // softmax per pixel pair (half the threads), write (w,w') pairs + labels
    if (h == 0) {
        float2 sv2 = *(const float2*)&sh_sv[2*pi];
        float w0[9], w1[9];
        float dmin0 = 3.0e38f, dmin1 = 3.0e38f;
        #pragma unroll
        for (int k = 0; k < 9; k++) {
            float a0, a1; f2_unpack(acc[k], a0, a1);
            float2 pr = *(const float2*)&sh_red[pi*18 + 2*k];
            float gq = sh_gsq[k];
            float d0 = valid[k] ? (sv2.x - 2.f*(a0 + pr.x) + gq) : 3.0e38f;
            float d1 = valid[k] ? (sv2.y - 2.f*(a1 + pr.y) + gq) : 3.0e38f;
            w0[k] = d0; w1[k] = d1;
            dmin0 = fminf(dmin0, d0); dmin1 = fminf(dmin1, d1);
        }
        if (last) {                      // first argmin == argmax(affinity)
            int kb0 = 0, kb1 = 0; float b0 = w0[0], b1 = w1[0];
            #pragma unroll
            for (int k = 1; k < 9; k++) {
                if (w0[k] < b0) { b0 = w0[k]; kb0 = k; }
                if (w1[k] < b1) { b1 = w1[k]; kb1 = k; }
            }
            int p0 = 2*pi;
            size_t o = (size_t)bb*HW + (size_t)(y0 + (p0>>5))*Wn + (x0 + (p0&31));
            *(float2*)&out_labels[o] = make_float2((float)nbr[kb0], (float)nbr[kb1]);
        }
        float s0 = 0.f, s1 = 0.f;
        #pragma unroll
        for (int k = 0; k < 9; k++) {
            float e0 = __expf(dmin0 - w0[k]);
            float e1 = __expf(dmin1 - w1[k]);
            w0[k] = e0; w1[k] = e1; s0 += e0; s1 += e1;
        }
        float i0 = 1.f/s0, i1 = 1.f/s1;
        ull wp[9]; float psum[9];
        #pragma unroll
        for (int k = 0; k < 9; k++) {
            float a = w0[k]*i0, b2 = w1[k]*i1;
            wp[k] = f2_pack(a, b2);
            psum[k] = a + b2;
        }
        float* wrow = &sh_w2[pi*20];
        #pragma unroll
        for (int k2 = 0; k2 < 4; k2++) {
            ulonglong2 t2; t2.x = wp[2*k2]; t2.y = wp[2*k2+1];
            *(ulonglong2*)&wrow[4*k2] = t2;
        }
        *(ull*)&wrow[16] = wp[8];

        #pragma unroll
        for (int k = 0; k < 9; k++) {     // denom: reduce over 128 threads
            float s = psum[k];
            s += __shfl_down_sync(0xffffffffu, s, 16);
            s += __shfl_down_sync(0xffffffffu, s, 8);
            s += __shfl_down_sync(0xffffffffu, s, 4);
            s += __shfl_down_sync(0xffffffffu, s, 2);
            s += __shfl_down_sync(0xffffffffu, s, 1);
            if ((tid & 31) == 0) sh_dred[k*4 + (tid >> 5)] = s;
        }
    }
    __syncthreads();
    if (tid < 9 && valid[tid]) {
        float s = sh_dred[tid*4] + sh_dred[tid*4+1] + sh_dred[tid*4+2] + sh_dred[tid*4+3];
        atomicAdd(&g_denom2[par][bb*NSPIX + nbr[tid]], s);
    }

    // phase 2: packed weighted sums. warp owns 32 pixels (16 pairs);
    // lane owns channels l and l+32.
    {
        const int wd = tid >> 5, l = tid & 31;
        ull m0[9], m1[9];
        #pragma unroll
        for (int k = 0; k < 9; k++) { m0[k] = 0ull; m1[k] = 0ull; }
        for (int jj = 0; jj < 16; jj++) {
            int p2 = (wd << 5) + (jj << 1);
            ull v0 = *(const ull*)&sh_f[l*S        + p2];
            ull v1 = *(const ull*)&sh_f[(l+32)*S   + p2];
            const float* wrow = &sh_w2[(p2 >> 1)*20];
            ulonglong2 wA = *(const ulonglong2*)&wrow[0];
            ulonglong2 wB = *(const ulonglong2*)&wrow[4];
            ulonglong2 wC = *(const ulonglong2*)&wrow[8];
            ulonglong2 wD = *(const ulonglong2*)&wrow[12];
            ull        wE = *(const ull*)&wrow[16];
            ffma2(m0[0], wA.x, v0);  ffma2(m1[0], wA.x, v1);
            ffma2(m0[1], wA.y, v0);  ffma2(m1[1], wA.y, v1);
            ffma2(m0[2], wB.x, v0);  ffma2(m1[2], wB.x, v1);
            ffma2(m0[3], wB.y, v0);  ffma2(m1[3], wB.y, v1);
            ffma2(m0[4], wC.x, v0);  ffma2(m1[4], wC.x, v1);
            ffma2(m0[5], wC.y, v0);  ffma2(m1[5], wC.y, v1);
            ffma2(m0[6], wD.x, v0);  ffma2(m1[6], wD.x, v1);
            ffma2(m0[7], wD.y, v0);  ffma2(m1[7], wD.y, v1);
            ffma2(m0[8], wE,   v0);  ffma2(m1[8], wE,   v1);
        }
        #pragma unroll
        for (int k = 0; k < 9; k++) {
            float a, b2;
            f2_unpack(m0[k], a, b2);
            atomicAdd(&sh_M[k*64 + l], a + b2);
            f2_unpack(m1[k], a, b2);
            atomicAdd(&sh_M[k*64 + l + 32], a + b2);
        }
    }
    __syncthreads();

    // flush numerators
    for (int idx = tid; idx < 576; idx += 256) {
        int k = idx >> 6;
        if (valid[k])
            atomicAdd(&g_numer[(bb*NSPIX + nbr[k])*Cn + (idx & 63)], sh_M[idx]);
    }
}

// ---------------------------------------------------------------------------
// update + self-zero (denom double-buffered to avoid read/zero race)
// ---------------------------------------------------------------------------
__global__ void update_kernel(float* __restrict__ out_spix, int it, int last)
{
    int idx = blockIdx.x*256 + threadIdx.x;     // 65536
    int par = it & 1;
    float val = g_numer[idx] / (g_denom2[par][idx >> 6] + 1e-16f);
    g_spix[idx] = val;
    if (last) out_spix[idx] = val;
    g_numer[idx] = 0.f;
    if (idx < Bn*NSPIX) g_denom2[1 - par][idx] = 0.f;
}

// ---------------------------------------------------------------------------
extern "C" void kernel_launch(void* const* d_in, const int* in_sizes, int n_in,
                              void* d_out, int out_size)
{
    const float* f = (const float*)d_in[0];
    float* out        = (float*)d_out;
    float* out_spix   = out;                       // (4,256,64)
    float* out_labels = out + Bn*NSPIX*Cn;         // (4,262144)

    cudaFuncSetAttribute(ssn_iter_kernel,
                         cudaFuncAttributeMaxDynamicSharedMemorySize, SMEM_BYTES);

    init_kernel<<<dim3(NSPIX, Bn), 256>>>(f);
    for (int it = 0; it < 5; it++) {
        ssn_iter_kernel<<<dim3(4, NSPIX, Bn), 256, SMEM_BYTES>>>(
            f, out_labels, it, it == 4);
        update_kernel<<<256, 256>>>(out_spix, it, it == 4);
    }
}